// round 2
// baseline (speedup 1.0000x reference)
#include <cuda_runtime.h>

// IF spiking neuron, T=4. Pure streaming: 128 MiB in + 128 MiB out.
// R2: each thread owns TWO block-strided float4 lanes across all 4 timesteps
// (8 independent loads -> MLP=8), with streaming cache hints (__ldcs/__stcs)
// since no byte is ever reused.

#define TSTEPS 4
#define LANES  2   // float4 lanes per thread

__global__ __launch_bounds__(256, 8)
void if_kernel(const float4* __restrict__ x,
               const float*  __restrict__ thresh,
               float4* __restrict__ out,
               int stride4)
{
    // Block covers LANES*256 consecutive float4s; each lane block-strided.
    int base = blockIdx.x * (blockDim.x * LANES) + threadIdx.x;

    const float th = __ldg(thresh);

    // Batch all 8 independent strided loads up-front (MLP=8 per thread).
    float4 xt[LANES][TSTEPS];
#pragma unroll
    for (int l = 0; l < LANES; l++) {
        int idx = base + l * blockDim.x;
#pragma unroll
        for (int t = 0; t < TSTEPS; t++)
            xt[l][t] = __ldcs(&x[idx + t * stride4]);
    }

    float4 sp[LANES][TSTEPS];

#pragma unroll
    for (int l = 0; l < LANES; l++) {
        float* xf = reinterpret_cast<float*>(xt[l]);
        float* sf = reinterpret_cast<float*>(sp[l]);
#pragma unroll
        for (int c = 0; c < 4; c++) {
            float m = 0.5f * th;
#pragma unroll
            for (int t = 0; t < TSTEPS; t++) {
                m += xf[t * 4 + c];
                float s = (m >= th) ? th : 0.0f;
                sf[t * 4 + c] = s;
                m -= s;
            }
        }
    }

#pragma unroll
    for (int l = 0; l < LANES; l++) {
        int idx = base + l * blockDim.x;
#pragma unroll
        for (int t = 0; t < TSTEPS; t++)
            __stcs(&out[idx + t * stride4], sp[l][t]);
    }
}

extern "C" void kernel_launch(void* const* d_in, const int* in_sizes, int n_in,
                              void* d_out, int out_size)
{
    const float* x      = (const float*)d_in[0];
    const float* thresh = (const float*)d_in[1];
    float* out          = (float*)d_out;

    int n = in_sizes[0];              // total elements (T * B*C*H*W) = 2^27
    int stride = n / TSTEPS;          // elements per timestep slab
    int stride4 = stride / 4;         // float4 units per slab = 8388608/4

    int threads = 256;
    int blocks = stride4 / (threads * LANES);   // 8388608/4/512 = 4096, exact
    if_kernel<<<blocks, threads>>>(
        (const float4*)x, thresh, (float4*)out, stride4);
}

// round 3
// speedup vs baseline: 1.1507x; 1.1507x over previous
#include <cuda_runtime.h>

// IF spiking neuron, T=4. Pure streaming: 128 MiB in + 128 MiB out.
// R3: exact R1 structure (MLP=4 per thread, fits in 32 regs) with ONE change:
// streaming stores (__stcs) so the write-once output doesn't pollute L2.

#define TSTEPS 4

__global__ __launch_bounds__(256)
void if_kernel(const float4* __restrict__ x,
               const float*  __restrict__ thresh,
               float4* __restrict__ out,
               int n4, int stride4)
{
    int i = blockIdx.x * blockDim.x + threadIdx.x;
    if (i >= n4) return;

    const float th = __ldg(thresh);

    // Batch all 4 strided loads up-front (independent -> MLP=4 per thread).
    float4 xt[TSTEPS];
#pragma unroll
    for (int t = 0; t < TSTEPS; t++)
        xt[t] = x[i + t * stride4];

    float4 sp[TSTEPS];
    float* xf = reinterpret_cast<float*>(xt);
    float* sf = reinterpret_cast<float*>(sp);

    // Per-component sequential membrane recurrence (4 independent chains).
#pragma unroll
    for (int c = 0; c < 4; c++) {
        float m = 0.5f * th;
#pragma unroll
        for (int t = 0; t < TSTEPS; t++) {
            m += xf[t * 4 + c];
            float s = (m >= th) ? th : 0.0f;
            sf[t * 4 + c] = s;
            m -= s;
        }
    }

#pragma unroll
    for (int t = 0; t < TSTEPS; t++)
        __stcs(&out[i + t * stride4], sp[t]);
}

extern "C" void kernel_launch(void* const* d_in, const int* in_sizes, int n_in,
                              void* d_out, int out_size)
{
    const float* x      = (const float*)d_in[0];
    const float* thresh = (const float*)d_in[1];
    float* out          = (float*)d_out;

    int n = in_sizes[0];              // total elements (T * B*C*H*W)
    int stride = n / TSTEPS;          // elements per timestep slab
    int stride4 = stride / 4;         // float4 units per slab
    int n4 = stride4;

    int threads = 256;
    int blocks = (n4 + threads - 1) / threads;   // 8192
    if_kernel<<<blocks, threads>>>(
        (const float4*)x, thresh, (float4*)out, n4, stride4);
}